// round 2
// baseline (speedup 1.0000x reference)
#include <cuda_runtime.h>

#define MP1 524288
#define NXP 32768
#define PP  128
#define HT  128
#define HE  64

// scratch (no cudaMalloc allowed)
__device__ float g_part[2][PP];
__device__ float g_c[PP + 1];   // c[0..127], d0 at [128]

// packed f32x2 helpers (sm_103a FFMA2)
__device__ __forceinline__ void ffma2(unsigned long long& d,
                                      unsigned long long a,
                                      unsigned long long b) {
    asm("fma.rn.f32x2 %0, %1, %2, %0;" : "+l"(d) : "l"(a), "l"(b));
}
__device__ __forceinline__ unsigned long long pack2(float v) {
    unsigned long long r;
    asm("mov.b64 %0, {%1, %1};" : "=l"(r) : "f"(v));
    return r;
}
__device__ __forceinline__ void unpack2(unsigned long long p, float& lo, float& hi) {
    asm("mov.b64 {%0, %1}, %2;" : "=f"(lo), "=f"(hi) : "l"(p));
}

// ---------------------------------------------------------------- branch
// grid 256: p = blockIdx&127, half = blockIdx>>7. Partials to g_part.
__global__ __launch_bounds__(1024, 2) void k_branch(const float* __restrict__ Wb,
                                                    const float* __restrict__ a,
                                                    const float* __restrict__ bb) {
    const int p = blockIdx.x & 127, half = blockIdx.x >> 7;
    const int base = half * (MP1 / 8);            // in float4 units
    const float4* row = reinterpret_cast<const float4*>(Wb + (size_t)p * MP1) + base;
    const float4* a4  = reinterpret_cast<const float4*>(a) + base;
    float s = 0.f;
#pragma unroll 8
    for (int i = threadIdx.x; i < MP1 / 8; i += 1024) {
        float4 w = row[i], v = a4[i];
        s += w.x * v.x + w.y * v.y + w.z * v.z + w.w * v.w;
    }
    __shared__ float red[32];
    for (int o = 16; o; o >>= 1) s += __shfl_down_sync(0xffffffffu, s, o);
    if ((threadIdx.x & 31) == 0) red[threadIdx.x >> 5] = s;
    __syncthreads();
    if (threadIdx.x < 32) {
        float v = red[threadIdx.x];
        for (int o = 16; o; o >>= 1) v += __shfl_down_sync(0xffffffffu, v, o);
        if (threadIdx.x == 0) g_part[half][p] = v + (half == 0 ? bb[p] : 0.f);
    }
}

// ------------------------------------------------- c = Wt3^T b, d0 = b.bt3
__global__ void k_coeff(const float* __restrict__ Wt3, const float* __restrict__ bt3) {
    __shared__ float sb[PP];
    __shared__ float w4[4];
    int k = threadIdx.x;
    sb[k] = g_part[0][k] + g_part[1][k];
    __syncthreads();
    float s = 0.f;
#pragma unroll 8
    for (int p = 0; p < PP; ++p) s += sb[p] * Wt3[p * PP + k];
    g_c[k] = s;
    float v = sb[k] * bt3[k];
    for (int o = 16; o; o >>= 1) v += __shfl_down_sync(0xffffffffu, v, o);
    if ((k & 31) == 0) w4[k >> 5] = v;
    __syncthreads();
    if (k == 0) g_c[PP] = w4[0] + w4[1] + w4[2] + w4[3];
}

// ---------------------------------------------------------------- main
// smem layout (floats)
#define WPAD 132
#define EPAD 68
#define OFF_WT2 0                    // 128*132 = 16896
#define OFF_WE2 16896                // 64*68   = 4352
#define OFF_C   21248
#define OFF_W0  21376
#define OFF_ZC  21504
#define OFF_BT2 21632
#define OFF_P   21760
#define OFF_Q   21824
#define OFF_BE1 21888
#define OFF_BE2 21952
#define OFF_W3  22016
#define OFF_D0  22080
#define OFF_LANE 22084
// per-lane region
#define L_H1 0        // 128 * 4 (float4 jets per unit)
#define L_E1 512      // 64 * 12 (9 comps padded to 12)
#define L_EP 1280     // 2 * 64 * 12
#define L_U  2816     // 4 (+pad)
#define L_FP 2824     // 2 warps * 8
#define LANE_SZ 2840
#define NLANE 2
#define TPB 256
#define GRID 296
#define STRIDE (GRID * NLANE)                 // 592
#define ITERS ((NXP + STRIDE - 1) / STRIDE)   // 56
#define SMEM_FLOATS (OFF_LANE + NLANE * LANE_SZ)

__global__ __launch_bounds__(TPB, 2) void k_main(
    const float* __restrict__ x, const float* __restrict__ tptr,
    const float* __restrict__ Wt1, const float* __restrict__ bt1,
    const float* __restrict__ Wt2, const float* __restrict__ bt2,
    const float* __restrict__ We1, const float* __restrict__ be1,
    const float* __restrict__ We2, const float* __restrict__ be2,
    const float* __restrict__ We3, float* __restrict__ out)
{
    extern __shared__ float sm[];
    const int tid = threadIdx.x;

    // ---- stage all weights into smem (padded rows for conflict-free f4 loads)
    {
        const float4* src = reinterpret_cast<const float4*>(Wt2);
#pragma unroll
        for (int i = tid; i < HT * HT / 4; i += TPB) {
            int e = i * 4, j = e >> 7, k = e & 127;
            *reinterpret_cast<float4*>(&sm[OFF_WT2 + j * WPAD + k]) = src[i];
        }
        const float4* se = reinterpret_cast<const float4*>(We2);
#pragma unroll
        for (int i = tid; i < HE * HE / 4; i += TPB) {
            int e = i * 4, j = e >> 6, k = e & 63;
            *reinterpret_cast<float4*>(&sm[OFF_WE2 + j * EPAD + k]) = se[i];
        }
        float tv = *tptr;
        if (tid < 128) {
            sm[OFF_C + tid]   = g_c[tid];
            float w0 = Wt1[2 * tid];
            sm[OFF_W0 + tid]  = w0;
            sm[OFF_ZC + tid]  = Wt1[2 * tid + 1] * tv + bt1[tid];
            sm[OFF_BT2 + tid] = bt2[tid];
        }
        if (tid < 64) {
            sm[OFF_P + tid]   = We1[2 * tid];
            sm[OFF_Q + tid]   = We1[2 * tid + 1];
            sm[OFF_BE1 + tid] = be1[tid];
            sm[OFF_BE2 + tid] = be2[tid];
            sm[OFF_W3 + tid]  = We3[tid];
        }
        if (tid == 0) sm[OFF_D0] = g_c[PP];
    }
    __syncthreads();

    const int lane = tid >> 7;          // point-lane within block
    const int j    = tid & 127;         // unit index within lane
    float* L = sm + OFF_LANE + lane * LANE_SZ;
    const int wl  = j & 31;
    const int wrp = j >> 5;
    const int lane_gid = blockIdx.x * NLANE + lane;

    for (int it = 0; it < ITERS; ++it) {
        const int pt = lane_gid + it * STRIDE;
        const bool active = pt < NXP;

        // ---- phase 1: trunk layer-1 jets (1-var, only z1' nonzero)
        {
            float xi = active ? x[pt] : 0.f;
            float w0 = sm[OFF_W0 + j];
            float T  = tanhf(w0 * xi + sm[OFF_ZC + j]);
            float s  = 1.f - T * T;
            float d2 = -2.f * T * s;
            float d3 = -2.f * s * (1.f - 3.f * T * T);
            float w2 = w0 * w0;
            *reinterpret_cast<float4*>(&L[L_H1 + j * 4]) =
                make_float4(T, s * w0, d2 * w2, d3 * w2 * w0);
        }
        __syncthreads();

        // ---- phase 2: trunk layer-2 GEMV (4 streams, packed f32x2) + tanh jet
        {
            unsigned long long acc01, acc23 = 0ull;
            {
                float b0 = sm[OFF_BT2 + j];
                asm("mov.b64 %0, {%1, %2};" : "=l"(acc01) : "f"(b0), "f"(0.f));
            }
            const float4* wrow = reinterpret_cast<const float4*>(&sm[OFF_WT2 + j * WPAD]);
            const ulonglong2* hj = reinterpret_cast<const ulonglong2*>(&L[L_H1]);
#pragma unroll
            for (int k4 = 0; k4 < 32; ++k4) {
                float4 w = wrow[k4];
                ulonglong2 h0 = hj[4 * k4 + 0];
                ulonglong2 h1 = hj[4 * k4 + 1];
                ulonglong2 h2 = hj[4 * k4 + 2];
                ulonglong2 h3 = hj[4 * k4 + 3];
                unsigned long long wp;
                wp = pack2(w.x); ffma2(acc01, wp, h0.x); ffma2(acc23, wp, h0.y);
                wp = pack2(w.y); ffma2(acc01, wp, h1.x); ffma2(acc23, wp, h1.y);
                wp = pack2(w.z); ffma2(acc01, wp, h2.x); ffma2(acc23, wp, h2.y);
                wp = pack2(w.w); ffma2(acc01, wp, h3.x); ffma2(acc23, wp, h3.y);
            }
            float acc0, acc1, acc2, acc3;
            unpack2(acc01, acc0, acc1);
            unpack2(acc23, acc2, acc3);
            float T  = tanhf(acc0);
            float s  = 1.f - T * T;
            float d2 = -2.f * T * s;
            float d3 = -2.f * s * (1.f - 3.f * T * T);
            float g1 = s * acc1;
            float g2 = s * acc2 + d2 * acc1 * acc1;
            float g3 = s * acc3 + 3.f * d2 * acc1 * acc2 + d3 * acc1 * acc1 * acc1;
            float cc = sm[OFF_C + j];
            __syncthreads();   // everyone finished reading L_H1
            *reinterpret_cast<float4*>(&L[L_H1 + j * 4]) =
                make_float4(cc * T, cc * g1, cc * g2, cc * g3);
        }
        __syncthreads();
        {   // per-stream reduction: warp wrp reduces stream wrp
            float v = L[L_H1 + wl * 4 + wrp] + L[L_H1 + (wl + 32) * 4 + wrp]
                    + L[L_H1 + (wl + 64) * 4 + wrp] + L[L_H1 + (wl + 96) * 4 + wrp];
            for (int o = 16; o; o >>= 1) v += __shfl_down_sync(0xffffffffu, v, o);
            if (wl == 0) {
                if (wrp == 0) v += sm[OFF_D0];
                L[L_U + wrp] = v;
            }
        }
        __syncthreads();

        // ---- phase 3: EnergyNet layer-1 2-var jets (seeds y=u, z=u_x)
        if (j < 64) {
            float y = L[L_U + 0], z = L[L_U + 1];
            float p = sm[OFF_P + j], q = sm[OFF_Q + j];
            float T  = tanhf(p * y + q * z + sm[OFF_BE1 + j]);
            float s  = 1.f - T * T;
            float d2 = -2.f * T * s;
            float d3 = -2.f * s * (1.f - 3.f * T * T);
            float* e = &L[L_E1 + j * 12];
            *reinterpret_cast<float4*>(e)     = make_float4(T, s * p, s * q, d2 * p * p);
            *reinterpret_cast<float4*>(e + 4) = make_float4(d2 * p * q, d2 * q * q,
                                                            d3 * p * p * q, d3 * p * q * q);
            e[8] = d3 * q * q * q;
        }
        __syncthreads();

        // ---- phase 4: EnergyNet layer-2 GEMV, 9 streams (4x f32x2 + 1 scalar)
        {
            const int j2 = j & 63, half = j >> 6;
            unsigned long long A0 = 0ull, A1 = 0ull, A2 = 0ull, A3 = 0ull;
            float a8 = 0.f;
            const float4* wrow =
                reinterpret_cast<const float4*>(&sm[OFF_WE2 + j2 * EPAD + half * 32]);
            const float* eb = &L[L_E1 + half * 32 * 12];
#pragma unroll
            for (int k4 = 0; k4 < 8; ++k4) {
                float4 w = wrow[k4];
#pragma unroll
                for (int ss = 0; ss < 4; ++ss) {
                    const float* e = eb + (4 * k4 + ss) * 12;
                    float wk = (ss == 0) ? w.x : (ss == 1) ? w.y : (ss == 2) ? w.z : w.w;
                    ulonglong2 eA = *reinterpret_cast<const ulonglong2*>(e);
                    ulonglong2 eB = *reinterpret_cast<const ulonglong2*>(e + 4);
                    float  eC = e[8];
                    unsigned long long wp = pack2(wk);
                    ffma2(A0, wp, eA.x); ffma2(A1, wp, eA.y);
                    ffma2(A2, wp, eB.x); ffma2(A3, wp, eB.y);
                    a8 = fmaf(wk, eC, a8);
                }
            }
            float a0, a1, a2, a3, a4, a5, a6, a7;
            unpack2(A0, a0, a1); unpack2(A1, a2, a3);
            unpack2(A2, a4, a5); unpack2(A3, a6, a7);
            float* dst = &L[L_EP + (half * 64 + j2) * 12];
            *reinterpret_cast<float4*>(dst)     = make_float4(a0, a1, a2, a3);
            *reinterpret_cast<float4*>(dst + 4) = make_float4(a4, a5, a6, a7);
            dst[8] = a8;
        }
        __syncthreads();

        // ---- phase 5: combine halves, multivariate tanh jet, We3 reduction
        if (j < 64) {
            const float* p0 = &L[L_EP + j * 12];
            const float* p1 = &L[L_EP + (64 + j) * 12];
            float a0   = p0[0] + p1[0] + sm[OFF_BE2 + j];
            float ay   = p0[1] + p1[1], az   = p0[2] + p1[2];
            float ayy  = p0[3] + p1[3], ayz  = p0[4] + p1[4], azz = p0[5] + p1[5];
            float ayyz = p0[6] + p1[6], ayzz = p0[7] + p1[7], azzz = p0[8] + p1[8];
            float T  = tanhf(a0);
            float s  = 1.f - T * T;
            float d2 = -2.f * T * s;
            float d3 = -2.f * s * (1.f - 3.f * T * T);
            float vyy  = s * ayy  + d2 * ay * ay;
            float vzz  = s * azz  + d2 * az * az;
            float vyyz = s * ayyz + d2 * (ayy * az + 2.f * ayz * ay) + d3 * ay * ay * az;
            float vyzz = s * ayzz + d2 * (azz * ay + 2.f * ayz * az) + d3 * ay * az * az;
            float vzzz = s * azzz + 3.f * d2 * azz * az + d3 * az * az * az;
            float w3 = sm[OFF_W3 + j];
            float r0 = w3 * vyy, r1 = w3 * vzz, r2 = w3 * vyyz, r3 = w3 * vyzz, r4 = w3 * vzzz;
            for (int o = 16; o; o >>= 1) {
                r0 += __shfl_down_sync(0xffffffffu, r0, o);
                r1 += __shfl_down_sync(0xffffffffu, r1, o);
                r2 += __shfl_down_sync(0xffffffffu, r2, o);
                r3 += __shfl_down_sync(0xffffffffu, r3, o);
                r4 += __shfl_down_sync(0xffffffffu, r4, o);
            }
            if (wl == 0) {
                float* fp = &L[L_FP + wrp * 8];
                fp[0] = r0; fp[1] = r1; fp[2] = r2; fp[3] = r3; fp[4] = r4;
            }
        }
        __syncthreads();
        if (j == 0 && active) {
            float Fyy  = L[L_FP + 0] + L[L_FP + 8];
            float Fzz  = L[L_FP + 1] + L[L_FP + 9];
            float Fyyz = L[L_FP + 2] + L[L_FP + 10];
            float Fyzz = L[L_FP + 3] + L[L_FP + 11];
            float Fzzz = L[L_FP + 4] + L[L_FP + 12];
            float u1 = L[L_U + 1], u2 = L[L_U + 2], u3 = L[L_U + 3];
            // -F_yx + F_zxx with exact F_yz cancellation
            out[pt] = -Fyy * u1 + Fzz * u3 + Fyyz * u1 * u1
                    + 2.f * Fyzz * u1 * u2 + Fzzz * u2 * u2;
        }
        // next iteration's L_H1 writers are safe: last L_H1 readers synced above
    }
}

// ---------------------------------------------------------------- launch
extern "C" void kernel_launch(void* const* d_in, const int* in_sizes, int n_in,
                              void* d_out, int out_size) {
    const float* a   = (const float*)d_in[0];
    const float* x   = (const float*)d_in[1];
    const float* t   = (const float*)d_in[2];
    const float* Wb  = (const float*)d_in[3];
    const float* bb  = (const float*)d_in[4];
    const float* Wt1 = (const float*)d_in[5];
    const float* bt1 = (const float*)d_in[6];
    const float* Wt2 = (const float*)d_in[7];
    const float* bt2 = (const float*)d_in[8];
    const float* Wt3 = (const float*)d_in[9];
    const float* bt3 = (const float*)d_in[10];
    const float* We1 = (const float*)d_in[11];
    const float* be1 = (const float*)d_in[12];
    const float* We2 = (const float*)d_in[13];
    const float* be2 = (const float*)d_in[14];
    const float* We3 = (const float*)d_in[15];
    (void)in_sizes; (void)n_in;
    float* out = (float*)d_out; (void)out_size;

    k_branch<<<256, 1024>>>(Wb, a, bb);
    k_coeff<<<1, 128>>>(Wt3, bt3);

    size_t smem = SMEM_FLOATS * sizeof(float);
    cudaFuncSetAttribute(k_main, cudaFuncAttributeMaxDynamicSharedMemorySize, (int)smem);
    k_main<<<GRID, TPB, smem>>>(x, t, Wt1, bt1, Wt2, bt2,
                                We1, be1, We2, be2, We3, out);
}

// round 3
// speedup vs baseline: 2.6038x; 2.6038x over previous
#include <cuda_runtime.h>

#define MP1 524288
#define NXP 32768
#define PP  128
#define HT  128
#define HE  64

// scratch (no cudaMalloc allowed)
__device__ float g_part[2][PP];
__device__ float g_c[PP + 1];   // c[0..127], d0 at [128]

// ---------------------------------------------------------------- branch
// grid 256: p = blockIdx&127, half = blockIdx>>7. Partials to g_part.
__global__ __launch_bounds__(1024, 2) void k_branch(const float* __restrict__ Wb,
                                                    const float* __restrict__ a,
                                                    const float* __restrict__ bb) {
    const int p = blockIdx.x & 127, half = blockIdx.x >> 7;
    const int base = half * (MP1 / 8);            // in float4 units
    const float4* row = reinterpret_cast<const float4*>(Wb + (size_t)p * MP1) + base;
    const float4* a4  = reinterpret_cast<const float4*>(a) + base;
    float s = 0.f;
#pragma unroll 8
    for (int i = threadIdx.x; i < MP1 / 8; i += 1024) {
        float4 w = row[i], v = a4[i];
        s += w.x * v.x + w.y * v.y + w.z * v.z + w.w * v.w;
    }
    __shared__ float red[32];
    for (int o = 16; o; o >>= 1) s += __shfl_down_sync(0xffffffffu, s, o);
    if ((threadIdx.x & 31) == 0) red[threadIdx.x >> 5] = s;
    __syncthreads();
    if (threadIdx.x < 32) {
        float v = red[threadIdx.x];
        for (int o = 16; o; o >>= 1) v += __shfl_down_sync(0xffffffffu, v, o);
        if (threadIdx.x == 0) g_part[half][p] = v + (half == 0 ? bb[p] : 0.f);
    }
}

// ------------------------------------------------- c = Wt3^T b, d0 = b.bt3
__global__ void k_coeff(const float* __restrict__ Wt3, const float* __restrict__ bt3) {
    __shared__ float sb[PP];
    __shared__ float w4[4];
    int k = threadIdx.x;
    sb[k] = g_part[0][k] + g_part[1][k];
    __syncthreads();
    float s = 0.f;
#pragma unroll 8
    for (int p = 0; p < PP; ++p) s += sb[p] * Wt3[p * PP + k];
    g_c[k] = s;
    float v = sb[k] * bt3[k];
    for (int o = 16; o; o >>= 1) v += __shfl_down_sync(0xffffffffu, v, o);
    if ((k & 31) == 0) w4[k >> 5] = v;
    __syncthreads();
    if (k == 0) g_c[PP] = w4[0] + w4[1] + w4[2] + w4[3];
}

// ---------------------------------------------------------------- main
// smem layout (floats)
#define WPAD 132
#define EPAD 68
#define OFF_WT2 0                    // 128*132 = 16896
#define OFF_WE2 16896                // 64*68   = 4352
#define OFF_C   21248
#define OFF_W0  21376
#define OFF_ZC  21504
#define OFF_BT2 21632
#define OFF_P   21760
#define OFF_Q   21824
#define OFF_BE1 21888
#define OFF_BE2 21952
#define OFF_W3  22016
#define OFF_D0  22080
#define OFF_WARP 22084
// per-warp (= per-point) region
#define W_H1 0        // 128 * 4 (float4 jets per unit)
#define W_E1 512      // 64 * 12 (9 comps padded to 12)
#define WARP_SZ 1280

#define TPB 512
#define PTS 16                                 // warps (= points) per block
#define GRID 148
#define STRIDE (GRID * PTS)                    // 2368
#define ITERS ((NXP + STRIDE - 1) / STRIDE)    // 14
#define SMEM_FLOATS (OFF_WARP + PTS * WARP_SZ) // 42564 -> 170256 B

__device__ __forceinline__ void jet3(float z, float& T, float& s, float& d2, float& d3) {
    T  = tanhf(z);
    s  = 1.f - T * T;
    d2 = -2.f * T * s;
    d3 = -2.f * s * (1.f - 3.f * T * T);
}

__global__ __launch_bounds__(TPB, 1) void k_main(
    const float* __restrict__ x, const float* __restrict__ tptr,
    const float* __restrict__ Wt1, const float* __restrict__ bt1,
    const float* __restrict__ Wt2, const float* __restrict__ bt2,
    const float* __restrict__ We1, const float* __restrict__ be1,
    const float* __restrict__ We2, const float* __restrict__ be2,
    const float* __restrict__ We3, float* __restrict__ out)
{
    extern __shared__ float sm[];
    const int tid = threadIdx.x;

    // ---- stage all weights into smem (padded rows for conflict-free f4 loads)
    {
        const float4* src = reinterpret_cast<const float4*>(Wt2);
#pragma unroll
        for (int i = tid; i < HT * HT / 4; i += TPB) {
            int e = i * 4, j = e >> 7, k = e & 127;
            *reinterpret_cast<float4*>(&sm[OFF_WT2 + j * WPAD + k]) = src[i];
        }
        const float4* se = reinterpret_cast<const float4*>(We2);
#pragma unroll
        for (int i = tid; i < HE * HE / 4; i += TPB) {
            int e = i * 4, j = e >> 6, k = e & 63;
            *reinterpret_cast<float4*>(&sm[OFF_WE2 + j * EPAD + k]) = se[i];
        }
        float tv = *tptr;
        if (tid < 128) {
            sm[OFF_C + tid]   = g_c[tid];
            float w0 = Wt1[2 * tid];
            sm[OFF_W0 + tid]  = w0;
            sm[OFF_ZC + tid]  = Wt1[2 * tid + 1] * tv + bt1[tid];
            sm[OFF_BT2 + tid] = bt2[tid];
        }
        if (tid < 64) {
            sm[OFF_P + tid]   = We1[2 * tid];
            sm[OFF_Q + tid]   = We1[2 * tid + 1];
            sm[OFF_BE1 + tid] = be1[tid];
            sm[OFF_BE2 + tid] = be2[tid];
            sm[OFF_W3 + tid]  = We3[tid];
        }
        if (tid == 0) sm[OFF_D0] = g_c[PP];
    }
    __syncthreads();

    const int w    = tid >> 5;          // warp = point lane
    const int lane = tid & 31;
    float* H1 = sm + OFF_WARP + w * WARP_SZ + W_H1;
    float* E1 = sm + OFF_WARP + w * WARP_SZ + W_E1;
    const int base_pt = blockIdx.x * PTS + w;

    for (int it = 0; it < ITERS; ++it) {
        const int pt = base_pt + it * STRIDE;
        const bool active = pt < NXP;
        const float xi = active ? x[pt] : 0.f;

        // ---- phase 1: trunk layer-1 jets (this warp's point)
#pragma unroll
        for (int m = 0; m < 4; ++m) {
            int j = lane + 32 * m;
            float w0 = sm[OFF_W0 + j];
            float T, s, d2, d3;
            jet3(fmaf(w0, xi, sm[OFF_ZC + j]), T, s, d2, d3);
            float w2 = w0 * w0;
            *reinterpret_cast<float4*>(&H1[4 * j]) =
                make_float4(T, s * w0, d2 * w2, d3 * w2 * w0);
        }
        __syncwarp();

        // ---- phase 2: trunk layer-2 GEMV, 4 rows x 4 streams per thread
        float a0[4], a1[4], a2[4], a3[4];
#pragma unroll
        for (int m = 0; m < 4; ++m) {
            a0[m] = sm[OFF_BT2 + lane + 32 * m];
            a1[m] = 0.f; a2[m] = 0.f; a3[m] = 0.f;
        }
        {
            const float4* hj = reinterpret_cast<const float4*>(H1);
#pragma unroll 8
            for (int k4 = 0; k4 < 32; ++k4) {
                float4 h0 = hj[4 * k4 + 0];
                float4 h1 = hj[4 * k4 + 1];
                float4 h2 = hj[4 * k4 + 2];
                float4 h3 = hj[4 * k4 + 3];
#pragma unroll
                for (int m = 0; m < 4; ++m) {
                    float4 wv = *reinterpret_cast<const float4*>(
                        &sm[OFF_WT2 + (lane + 32 * m) * WPAD + 4 * k4]);
                    a0[m] += wv.x * h0.x; a1[m] += wv.x * h0.y; a2[m] += wv.x * h0.z; a3[m] += wv.x * h0.w;
                    a0[m] += wv.y * h1.x; a1[m] += wv.y * h1.y; a2[m] += wv.y * h1.z; a3[m] += wv.y * h1.w;
                    a0[m] += wv.z * h2.x; a1[m] += wv.z * h2.y; a2[m] += wv.z * h2.z; a3[m] += wv.z * h2.w;
                    a0[m] += wv.w * h3.x; a1[m] += wv.w * h3.y; a2[m] += wv.w * h3.z; a3[m] += wv.w * h3.w;
                }
            }
        }
        // tanh jet + c-dot partials, butterfly reduce -> u jets on all lanes
        float p0 = 0.f, p1 = 0.f, p2 = 0.f, p3 = 0.f;
#pragma unroll
        for (int m = 0; m < 4; ++m) {
            int j = lane + 32 * m;
            float T, s, d2, d3;
            jet3(a0[m], T, s, d2, d3);
            float g1 = s * a1[m];
            float g2 = s * a2[m] + d2 * a1[m] * a1[m];
            float g3 = s * a3[m] + 3.f * d2 * a1[m] * a2[m] + d3 * a1[m] * a1[m] * a1[m];
            float cc = sm[OFF_C + j];
            p0 += cc * T; p1 += cc * g1; p2 += cc * g2; p3 += cc * g3;
        }
#pragma unroll
        for (int o = 16; o; o >>= 1) {
            p0 += __shfl_xor_sync(0xffffffffu, p0, o);
            p1 += __shfl_xor_sync(0xffffffffu, p1, o);
            p2 += __shfl_xor_sync(0xffffffffu, p2, o);
            p3 += __shfl_xor_sync(0xffffffffu, p3, o);
        }
        const float u0 = p0 + sm[OFF_D0], u1 = p1, u2 = p2, u3 = p3;

        // ---- phase 3: EnergyNet layer-1 2-var jets (seeds y=u0, z=u1)
#pragma unroll
        for (int m = 0; m < 2; ++m) {
            int e = lane + 32 * m;
            float pp = sm[OFF_P + e], qq = sm[OFF_Q + e];
            float T, s, d2, d3;
            jet3(pp * u0 + qq * u1 + sm[OFF_BE1 + e], T, s, d2, d3);
            float* eb = &E1[12 * e];
            *reinterpret_cast<float4*>(eb) = make_float4(T, s * pp, s * qq, d2 * pp * pp);
            *reinterpret_cast<float4*>(eb + 4) =
                make_float4(d2 * pp * qq, d2 * qq * qq, d3 * pp * pp * qq, d3 * pp * qq * qq);
            eb[8] = d3 * qq * qq * qq;
        }
        __syncwarp();

        // ---- phase 4: EnergyNet layer-2 GEMV, 2 rows x 9 streams per thread
        float b[2][9];
#pragma unroll
        for (int m = 0; m < 2; ++m)
#pragma unroll
            for (int s9 = 0; s9 < 9; ++s9) b[m][s9] = 0.f;
#pragma unroll 4
        for (int k4 = 0; k4 < 16; ++k4) {
            float4 wv0 = *reinterpret_cast<const float4*>(&sm[OFF_WE2 + lane * EPAD + 4 * k4]);
            float4 wv1 = *reinterpret_cast<const float4*>(&sm[OFF_WE2 + (lane + 32) * EPAD + 4 * k4]);
#pragma unroll
            for (int i = 0; i < 4; ++i) {
                const float* e = &E1[12 * (4 * k4 + i)];
                float4 eA = *reinterpret_cast<const float4*>(e);
                float4 eB = *reinterpret_cast<const float4*>(e + 4);
                float  eC = e[8];
                float wk0 = (i == 0) ? wv0.x : (i == 1) ? wv0.y : (i == 2) ? wv0.z : wv0.w;
                float wk1 = (i == 0) ? wv1.x : (i == 1) ? wv1.y : (i == 2) ? wv1.z : wv1.w;
                b[0][0] += wk0 * eA.x; b[0][1] += wk0 * eA.y; b[0][2] += wk0 * eA.z; b[0][3] += wk0 * eA.w;
                b[0][4] += wk0 * eB.x; b[0][5] += wk0 * eB.y; b[0][6] += wk0 * eB.z; b[0][7] += wk0 * eB.w;
                b[0][8] += wk0 * eC;
                b[1][0] += wk1 * eA.x; b[1][1] += wk1 * eA.y; b[1][2] += wk1 * eA.z; b[1][3] += wk1 * eA.w;
                b[1][4] += wk1 * eB.x; b[1][5] += wk1 * eB.y; b[1][6] += wk1 * eB.z; b[1][7] += wk1 * eB.w;
                b[1][8] += wk1 * eC;
            }
        }

        // ---- phase 5: multivariate tanh jet + We3 reduction (registers only)
        float q0 = 0.f, q1 = 0.f, q2 = 0.f, q3 = 0.f, q4 = 0.f;
#pragma unroll
        for (int m = 0; m < 2; ++m) {
            int o = lane + 32 * m;
            float az0  = b[m][0] + sm[OFF_BE2 + o];
            float ay   = b[m][1], az   = b[m][2];
            float ayy  = b[m][3], ayz  = b[m][4], azz = b[m][5];
            float ayyz = b[m][6], ayzz = b[m][7], azzz = b[m][8];
            float T, s, d2, d3;
            jet3(az0, T, s, d2, d3);
            float vyy  = s * ayy  + d2 * ay * ay;
            float vzz  = s * azz  + d2 * az * az;
            float vyyz = s * ayyz + d2 * (ayy * az + 2.f * ayz * ay) + d3 * ay * ay * az;
            float vyzz = s * ayzz + d2 * (azz * ay + 2.f * ayz * az) + d3 * ay * az * az;
            float vzzz = s * azzz + 3.f * d2 * azz * az + d3 * az * az * az;
            float w3 = sm[OFF_W3 + o];
            q0 += w3 * vyy; q1 += w3 * vzz; q2 += w3 * vyyz; q3 += w3 * vyzz; q4 += w3 * vzzz;
        }
#pragma unroll
        for (int o = 16; o; o >>= 1) {
            q0 += __shfl_xor_sync(0xffffffffu, q0, o);
            q1 += __shfl_xor_sync(0xffffffffu, q1, o);
            q2 += __shfl_xor_sync(0xffffffffu, q2, o);
            q3 += __shfl_xor_sync(0xffffffffu, q3, o);
            q4 += __shfl_xor_sync(0xffffffffu, q4, o);
        }
        if (lane == 0 && active) {
            // -F_yx + F_zxx with exact F_yz cancellation
            out[pt] = -q0 * u1 + q1 * u3 + q2 * u1 * u1
                    + 2.f * q3 * u1 * u2 + q4 * u2 * u2;
        }
        __syncwarp();   // protect H1/E1 reuse next iteration
    }
}

// ---------------------------------------------------------------- launch
extern "C" void kernel_launch(void* const* d_in, const int* in_sizes, int n_in,
                              void* d_out, int out_size) {
    const float* a   = (const float*)d_in[0];
    const float* x   = (const float*)d_in[1];
    const float* t   = (const float*)d_in[2];
    const float* Wb  = (const float*)d_in[3];
    const float* bb  = (const float*)d_in[4];
    const float* Wt1 = (const float*)d_in[5];
    const float* bt1 = (const float*)d_in[6];
    const float* Wt2 = (const float*)d_in[7];
    const float* bt2 = (const float*)d_in[8];
    const float* Wt3 = (const float*)d_in[9];
    const float* bt3 = (const float*)d_in[10];
    const float* We1 = (const float*)d_in[11];
    const float* be1 = (const float*)d_in[12];
    const float* We2 = (const float*)d_in[13];
    const float* be2 = (const float*)d_in[14];
    const float* We3 = (const float*)d_in[15];
    (void)in_sizes; (void)n_in;
    float* out = (float*)d_out; (void)out_size;

    k_branch<<<256, 1024>>>(Wb, a, bb);
    k_coeff<<<1, 128>>>(Wt3, bt3);

    size_t smem = SMEM_FLOATS * sizeof(float);
    cudaFuncSetAttribute(k_main, cudaFuncAttributeMaxDynamicSharedMemorySize, (int)smem);
    k_main<<<GRID, TPB, smem>>>(x, t, Wt1, bt1, Wt2, bt2,
                                We1, be1, We2, be2, We3, out);
}

// round 4
// speedup vs baseline: 2.8550x; 1.0965x over previous
#include <cuda_runtime.h>

#define MP1 524288
#define NXP 32768
#define PP  128
#define HT  128
#define HE  64

#define TPB   512
#define WARPS 16
#define GRID_A 148
#define STRIDE_A (GRID_A * WARPS)              // 2368
#define ITERS_A 14                             // ceil(32768/2368)
#define ROW_F4 (MP1 / 4)                       // 131072
#define CPB ((ROW_F4 + GRID_A - 1) / GRID_A)   // 886

#define GRID_B 296
#define STRIDE_B (GRID_B * WARPS)              // 4736
#define ITERS_B 7                              // ceil(32768/4736)

// scratch (static device arrays, no runtime alloc)
__device__ float  g_partA[PP][GRID_A];
__device__ float  g_c[PP + 1];                 // c[0..127], d0 at [128]
__device__ float4 g_jets[NXP][PP];             // per-point per-unit (T,g1,g2,g3)

__device__ __forceinline__ void jet3(float z, float& T, float& s, float& d2, float& d3) {
    T  = tanhf(z);
    s  = 1.f - T * T;
    d2 = -2.f * T * s;
    d3 = -2.f * s * (1.f - 3.f * T * T);
}

// ================================================================= pass A
// smem layout (floats)
#define WPAD 132
#define A_WT2 0                     // 128*132 = 16896
#define A_W0  16896
#define A_ZC  17024
#define A_BT2 17152
#define A_H   17280                 // 16 warps * 512
#define A_SMEM (A_H + WARPS * 512)  // 25472 floats = 101888 B

__global__ __launch_bounds__(TPB, 1) void k_A(
    const float* __restrict__ Wb, const float* __restrict__ a,
    const float* __restrict__ x,  const float* __restrict__ tptr,
    const float* __restrict__ Wt1, const float* __restrict__ bt1,
    const float* __restrict__ Wt2, const float* __restrict__ bt2)
{
    extern __shared__ float sm[];
    const int tid = threadIdx.x;

    {   // stage Wt2 (padded rows) + layer-1 constants
        const float4* src = reinterpret_cast<const float4*>(Wt2);
#pragma unroll
        for (int i = tid; i < HT * HT / 4; i += TPB) {
            int e = i * 4, j = e >> 7, k = e & 127;
            *reinterpret_cast<float4*>(&sm[A_WT2 + j * WPAD + k]) = src[i];
        }
        float tv = *tptr;
        if (tid < 128) {
            float w0 = Wt1[2 * tid];
            sm[A_W0 + tid]  = w0;
            sm[A_ZC + tid]  = Wt1[2 * tid + 1] * tv + bt1[tid];
            sm[A_BT2 + tid] = bt2[tid];
        }
    }
    __syncthreads();

    const int w    = tid >> 5;
    const int lane = tid & 31;
    float* H1 = sm + A_H + w * 512;
    const int base_pt = blockIdx.x * WARPS + w;

    // branch slice for this block: float4 columns [colbase, colend)
    const int colbase = blockIdx.x * CPB;
    const int colend  = min(colbase + CPB, ROW_F4);
    const float4* a4  = reinterpret_cast<const float4*>(a);
    const float4* Wb4 = reinterpret_cast<const float4*>(Wb);
    float part[8];
#pragma unroll
    for (int r = 0; r < 8; ++r) part[r] = 0.f;

    for (int it = 0; it < ITERS_A; ++it) {
        // ---- branch interleave: 2 chunks x 8 rows (rows w, w+16, ..., w+112)
        {
            int c0 = colbase + (it * 2 + 0) * 32 + lane;
            int c1 = colbase + (it * 2 + 1) * 32 + lane;
            bool v0 = c0 < colend, v1 = c1 < colend;
            float4 av0 = v0 ? a4[c0] : make_float4(0.f, 0.f, 0.f, 0.f);
            float4 av1 = v1 ? a4[c1] : make_float4(0.f, 0.f, 0.f, 0.f);
#pragma unroll
            for (int r = 0; r < 8; ++r) {
                const float4* wr = Wb4 + (size_t)(w + 16 * r) * ROW_F4;
                if (v0) {
                    float4 wv = __ldcs(wr + c0);
                    part[r] += wv.x * av0.x + wv.y * av0.y + wv.z * av0.z + wv.w * av0.w;
                }
                if (v1) {
                    float4 wv = __ldcs(wr + c1);
                    part[r] += wv.x * av1.x + wv.y * av1.y + wv.z * av1.z + wv.w * av1.w;
                }
            }
        }

        // ---- trunk phases 1-2 for this warp's point
        const int pt = base_pt + it * STRIDE_A;
        const bool active = pt < NXP;
        const float xi = active ? x[pt] : 0.f;

#pragma unroll
        for (int m = 0; m < 4; ++m) {
            int j = lane + 32 * m;
            float w0 = sm[A_W0 + j];
            float T, s, d2, d3;
            jet3(fmaf(w0, xi, sm[A_ZC + j]), T, s, d2, d3);
            float w2 = w0 * w0;
            *reinterpret_cast<float4*>(&H1[4 * j]) =
                make_float4(T, s * w0, d2 * w2, d3 * w2 * w0);
        }
        __syncwarp();

        float a0[4], a1[4], a2[4], a3[4];
#pragma unroll
        for (int m = 0; m < 4; ++m) {
            a0[m] = sm[A_BT2 + lane + 32 * m];
            a1[m] = 0.f; a2[m] = 0.f; a3[m] = 0.f;
        }
        {
            const float4* hj = reinterpret_cast<const float4*>(H1);
#pragma unroll 8
            for (int k4 = 0; k4 < 32; ++k4) {
                float4 h0 = hj[4 * k4 + 0];
                float4 h1 = hj[4 * k4 + 1];
                float4 h2 = hj[4 * k4 + 2];
                float4 h3 = hj[4 * k4 + 3];
#pragma unroll
                for (int m = 0; m < 4; ++m) {
                    float4 wv = *reinterpret_cast<const float4*>(
                        &sm[A_WT2 + (lane + 32 * m) * WPAD + 4 * k4]);
                    a0[m] += wv.x * h0.x; a1[m] += wv.x * h0.y; a2[m] += wv.x * h0.z; a3[m] += wv.x * h0.w;
                    a0[m] += wv.y * h1.x; a1[m] += wv.y * h1.y; a2[m] += wv.y * h1.z; a3[m] += wv.y * h1.w;
                    a0[m] += wv.z * h2.x; a1[m] += wv.z * h2.y; a2[m] += wv.z * h2.z; a3[m] += wv.z * h2.w;
                    a0[m] += wv.w * h3.x; a1[m] += wv.w * h3.y; a2[m] += wv.w * h3.z; a3[m] += wv.w * h3.w;
                }
            }
        }
        // tanh jet per output unit, write raw jets to scratch
        if (active) {
#pragma unroll
            for (int m = 0; m < 4; ++m) {
                int j = lane + 32 * m;
                float T, s, d2, d3;
                jet3(a0[m], T, s, d2, d3);
                float g1 = s * a1[m];
                float g2 = s * a2[m] + d2 * a1[m] * a1[m];
                float g3 = s * a3[m] + 3.f * d2 * a1[m] * a2[m] + d3 * a1[m] * a1[m] * a1[m];
                g_jets[pt][j] = make_float4(T, g1, g2, g3);
            }
        }
        __syncwarp();   // H1 reuse next iteration
    }

    // ---- write branch partials (deterministic, per-block)
#pragma unroll
    for (int r = 0; r < 8; ++r) {
        float v = part[r];
#pragma unroll
        for (int o = 16; o; o >>= 1) v += __shfl_down_sync(0xffffffffu, v, o);
        if (lane == 0) g_partA[w + 16 * r][blockIdx.x] = v;
    }
}

// ======================================================== coeff: b, c, d0
__global__ void k_coeff(const float* __restrict__ Wt3, const float* __restrict__ bt3,
                        const float* __restrict__ bb) {
    __shared__ float sb[PP];
    __shared__ float w4[4];
    int k = threadIdx.x;
    float b = bb[k];
#pragma unroll 4
    for (int i = 0; i < GRID_A; ++i) b += g_partA[k][i];
    sb[k] = b;
    __syncthreads();
    float s = 0.f;
#pragma unroll 8
    for (int p = 0; p < PP; ++p) s += sb[p] * Wt3[p * PP + k];
    g_c[k] = s;
    float v = sb[k] * bt3[k];
    for (int o = 16; o; o >>= 1) v += __shfl_down_sync(0xffffffffu, v, o);
    if ((k & 31) == 0) w4[k >> 5] = v;
    __syncthreads();
    if (k == 0) g_c[PP] = w4[0] + w4[1] + w4[2] + w4[3];
}

// ================================================================= pass B
// smem layout (floats)
#define EPAD 68
#define B_WE2 0                      // 64*68 = 4352
#define B_C   4352                   // 128
#define B_P   4480
#define B_Q   4544
#define B_BE1 4608
#define B_BE2 4672
#define B_W3  4736
#define B_D0  4800
#define B_E   4804                   // 16 warps * 768
#define B_SMEM (B_E + WARPS * 768)   // 17092 floats = 68368 B

__global__ __launch_bounds__(TPB, 2) void k_B(
    const float* __restrict__ We1, const float* __restrict__ be1,
    const float* __restrict__ We2, const float* __restrict__ be2,
    const float* __restrict__ We3, float* __restrict__ out)
{
    extern __shared__ float sm[];
    const int tid = threadIdx.x;

    {   // stage We2 (padded) + constants
        const float4* se = reinterpret_cast<const float4*>(We2);
#pragma unroll
        for (int i = tid; i < HE * HE / 4; i += TPB) {
            int e = i * 4, j = e >> 6, k = e & 63;
            *reinterpret_cast<float4*>(&sm[B_WE2 + j * EPAD + k]) = se[i];
        }
        if (tid < 128) sm[B_C + tid] = g_c[tid];
        if (tid < 64) {
            sm[B_P + tid]   = We1[2 * tid];
            sm[B_Q + tid]   = We1[2 * tid + 1];
            sm[B_BE1 + tid] = be1[tid];
            sm[B_BE2 + tid] = be2[tid];
            sm[B_W3 + tid]  = We3[tid];
        }
        if (tid == 0) sm[B_D0] = g_c[PP];
    }
    __syncthreads();

    const int w    = tid >> 5;
    const int lane = tid & 31;
    float* E1 = sm + B_E + w * 768;
    const int base_pt = blockIdx.x * WARPS + w;
    const float c0 = sm[B_C + lane], c1 = sm[B_C + lane + 32];
    const float c2 = sm[B_C + lane + 64], c3 = sm[B_C + lane + 96];
    const float d0 = sm[B_D0];

    for (int it = 0; it < ITERS_B; ++it) {
        const int pt = base_pt + it * STRIDE_B;
        const bool active = pt < NXP;

        // ---- c-dot over jets -> u jets (all lanes)
        float p0, p1, p2, p3;
        {
            float4 j0, j1, j2, j3;
            if (active) {
                j0 = g_jets[pt][lane];      j1 = g_jets[pt][lane + 32];
                j2 = g_jets[pt][lane + 64]; j3 = g_jets[pt][lane + 96];
            } else {
                j0 = j1 = j2 = j3 = make_float4(0.f, 0.f, 0.f, 0.f);
            }
            p0 = c0 * j0.x + c1 * j1.x + c2 * j2.x + c3 * j3.x;
            p1 = c0 * j0.y + c1 * j1.y + c2 * j2.y + c3 * j3.y;
            p2 = c0 * j0.z + c1 * j1.z + c2 * j2.z + c3 * j3.z;
            p3 = c0 * j0.w + c1 * j1.w + c2 * j2.w + c3 * j3.w;
        }
#pragma unroll
        for (int o = 16; o; o >>= 1) {
            p0 += __shfl_xor_sync(0xffffffffu, p0, o);
            p1 += __shfl_xor_sync(0xffffffffu, p1, o);
            p2 += __shfl_xor_sync(0xffffffffu, p2, o);
            p3 += __shfl_xor_sync(0xffffffffu, p3, o);
        }
        const float u0 = p0 + d0, u1 = p1, u2 = p2, u3 = p3;

        // ---- EnergyNet layer-1 2-var jets
#pragma unroll
        for (int m = 0; m < 2; ++m) {
            int e = lane + 32 * m;
            float pp = sm[B_P + e], qq = sm[B_Q + e];
            float T, s, d2, d3;
            jet3(pp * u0 + qq * u1 + sm[B_BE1 + e], T, s, d2, d3);
            float* eb = &E1[12 * e];
            *reinterpret_cast<float4*>(eb) = make_float4(T, s * pp, s * qq, d2 * pp * pp);
            *reinterpret_cast<float4*>(eb + 4) =
                make_float4(d2 * pp * qq, d2 * qq * qq, d3 * pp * pp * qq, d3 * pp * qq * qq);
            eb[8] = d3 * qq * qq * qq;
        }
        __syncwarp();

        // ---- EnergyNet layer-2 GEMV, 2 rows x 9 streams per thread
        float b[2][9];
#pragma unroll
        for (int m = 0; m < 2; ++m)
#pragma unroll
            for (int s9 = 0; s9 < 9; ++s9) b[m][s9] = 0.f;
#pragma unroll 4
        for (int k4 = 0; k4 < 16; ++k4) {
            float4 wv0 = *reinterpret_cast<const float4*>(&sm[B_WE2 + lane * EPAD + 4 * k4]);
            float4 wv1 = *reinterpret_cast<const float4*>(&sm[B_WE2 + (lane + 32) * EPAD + 4 * k4]);
#pragma unroll
            for (int i = 0; i < 4; ++i) {
                const float* e = &E1[12 * (4 * k4 + i)];
                float4 eA = *reinterpret_cast<const float4*>(e);
                float4 eB = *reinterpret_cast<const float4*>(e + 4);
                float  eC = e[8];
                float wk0 = (i == 0) ? wv0.x : (i == 1) ? wv0.y : (i == 2) ? wv0.z : wv0.w;
                float wk1 = (i == 0) ? wv1.x : (i == 1) ? wv1.y : (i == 2) ? wv1.z : wv1.w;
                b[0][0] += wk0 * eA.x; b[0][1] += wk0 * eA.y; b[0][2] += wk0 * eA.z; b[0][3] += wk0 * eA.w;
                b[0][4] += wk0 * eB.x; b[0][5] += wk0 * eB.y; b[0][6] += wk0 * eB.z; b[0][7] += wk0 * eB.w;
                b[0][8] += wk0 * eC;
                b[1][0] += wk1 * eA.x; b[1][1] += wk1 * eA.y; b[1][2] += wk1 * eA.z; b[1][3] += wk1 * eA.w;
                b[1][4] += wk1 * eB.x; b[1][5] += wk1 * eB.y; b[1][6] += wk1 * eB.z; b[1][7] += wk1 * eB.w;
                b[1][8] += wk1 * eC;
            }
        }

        // ---- multivariate tanh jet + We3 reduction
        float q0 = 0.f, q1 = 0.f, q2 = 0.f, q3 = 0.f, q4 = 0.f;
#pragma unroll
        for (int m = 0; m < 2; ++m) {
            int o = lane + 32 * m;
            float az0  = b[m][0] + sm[B_BE2 + o];
            float ay   = b[m][1], az   = b[m][2];
            float ayy  = b[m][3], ayz  = b[m][4], azz = b[m][5];
            float ayyz = b[m][6], ayzz = b[m][7], azzz = b[m][8];
            float T, s, d2, d3;
            jet3(az0, T, s, d2, d3);
            float vyy  = s * ayy  + d2 * ay * ay;
            float vzz  = s * azz  + d2 * az * az;
            float vyyz = s * ayyz + d2 * (ayy * az + 2.f * ayz * ay) + d3 * ay * ay * az;
            float vyzz = s * ayzz + d2 * (azz * ay + 2.f * ayz * az) + d3 * ay * az * az;
            float vzzz = s * azzz + 3.f * d2 * azz * az + d3 * az * az * az;
            float w3 = sm[B_W3 + o];
            q0 += w3 * vyy; q1 += w3 * vzz; q2 += w3 * vyyz; q3 += w3 * vyzz; q4 += w3 * vzzz;
        }
#pragma unroll
        for (int o = 16; o; o >>= 1) {
            q0 += __shfl_xor_sync(0xffffffffu, q0, o);
            q1 += __shfl_xor_sync(0xffffffffu, q1, o);
            q2 += __shfl_xor_sync(0xffffffffu, q2, o);
            q3 += __shfl_xor_sync(0xffffffffu, q3, o);
            q4 += __shfl_xor_sync(0xffffffffu, q4, o);
        }
        if (lane == 0 && active) {
            out[pt] = -q0 * u1 + q1 * u3 + q2 * u1 * u1
                    + 2.f * q3 * u1 * u2 + q4 * u2 * u2;
        }
        __syncwarp();   // E1 reuse next iteration
    }
}

// ---------------------------------------------------------------- launch
extern "C" void kernel_launch(void* const* d_in, const int* in_sizes, int n_in,
                              void* d_out, int out_size) {
    const float* a   = (const float*)d_in[0];
    const float* x   = (const float*)d_in[1];
    const float* t   = (const float*)d_in[2];
    const float* Wb  = (const float*)d_in[3];
    const float* bb  = (const float*)d_in[4];
    const float* Wt1 = (const float*)d_in[5];
    const float* bt1 = (const float*)d_in[6];
    const float* Wt2 = (const float*)d_in[7];
    const float* bt2 = (const float*)d_in[8];
    const float* Wt3 = (const float*)d_in[9];
    const float* bt3 = (const float*)d_in[10];
    const float* We1 = (const float*)d_in[11];
    const float* be1 = (const float*)d_in[12];
    const float* We2 = (const float*)d_in[13];
    const float* be2 = (const float*)d_in[14];
    const float* We3 = (const float*)d_in[15];
    (void)in_sizes; (void)n_in;
    float* out = (float*)d_out; (void)out_size;

    size_t smemA = A_SMEM * sizeof(float);
    cudaFuncSetAttribute(k_A, cudaFuncAttributeMaxDynamicSharedMemorySize, (int)smemA);
    k_A<<<GRID_A, TPB, smemA>>>(Wb, a, x, t, Wt1, bt1, Wt2, bt2);

    k_coeff<<<1, 128>>>(Wt3, bt3, bb);

    size_t smemB = B_SMEM * sizeof(float);
    cudaFuncSetAttribute(k_B, cudaFuncAttributeMaxDynamicSharedMemorySize, (int)smemB);
    k_B<<<GRID_B, TPB, smemB>>>(We1, be1, We2, be2, We3, out);
}